// round 16
// baseline (speedup 1.0000x reference)
#include <cuda_runtime.h>
#include <cuda_bf16.h>
#include <cstdint>

// Problem constants (fixed by the reference)
#define N_ATOMS   2048
#define N_RBF     16
#define N_HIDDEN  32
// centers c_k = k/3 (linspace(0,5,16)), gamma = 9. With m = 3d = k* + f:
// g_k = e^{-(m-k)^2} = P * rho^k * T[k*-k],
//   P = exp2(-L f (f+2k*)), rho = exp2(2 L f), T[j] = e^{-j^2}
// Packed: feat2[i] = (feat[2i], feat[2i+1]); per step LDS.64 + FMA2 + MUL2.
#define LOG2E     (1.4426950408889634f)
#define MAGIC     (12582912.0f)        // 1.5*2^23 round-to-nearest trick
#define MAGIC_I   (0x4B400000)

#define WARPS_PER_BLOCK 4              // block = ONE atom, 4 j-slices
#define BLOCK           128
#define NBLOCKS         N_ATOMS                       // 2048 blocks
#define JSL             (N_ATOMS / WARPS_PER_BLOCK)   // 512 j's per slice
#define NCHUNK          (JSL / 32)                    // 16 chunks
#define PAD_D2          (177.78f)      // m=40 -> U reads land in zero entries
#define D2_CUT_BITS     (0x41C80000u)  // bits of 25.0f
#define NBANKS          16
#define FP_SCALE        (4294967296.0) // 2^32 fixed-point scale

// device scratch (no runtime alloc allowed); zero-initialized at module load
__device__ unsigned long long g_isum[NBANKS];
__device__ unsigned int       g_count;

__device__ __forceinline__ float fast_ex2(float x) {
    float r; asm("ex2.approx.ftz.f32 %0, %1;" : "=f"(r) : "f"(x)); return r;
}
__device__ __forceinline__ float fast_rsq(float x) {
    float r; asm("rsqrt.approx.ftz.f32 %0, %1;" : "=f"(r) : "f"(x)); return r;
}
__device__ __forceinline__ float fast_rcp(float x) {
    float r; asm("rcp.approx.ftz.f32 %0, %1;" : "=f"(r) : "f"(x)); return r;
}
__device__ __forceinline__ uint32_t smem_u32(const void* p) {
    uint32_t a;
    asm("{ .reg .u64 t; cvta.to.shared.u64 t, %1; cvt.u32.u64 %0, t; }"
        : "=r"(a) : "l"(p));
    return a;
}

// Table-factored RBF, f32x2-packed, TWO independent ladder chains
// (u: feat2[0,2,4,6] stepping rho^4; v: feat2[1,3,5,7] stepping rho^4).
__device__ __forceinline__ void accum_rbf_f2(float d2, uint32_t uBase,
                                             unsigned long long feat2[8]) {
    const float d  = d2 * fast_rsq(d2);            // sqrt(d2)
    const float m3 = 3.0f * d;                     // m = 3d
    const float mm = m3 + MAGIC;                   // magic round-to-nearest
    const float kf = mm - MAGIC;                   // (float)k*
    const float f  = m3 - kf;                      // |f| <= 0.5
    const uint32_t addr = uBase + ((__float_as_uint(mm) - MAGIC_I) << 3);
    const float s2 = -LOG2E * f;
    const float s1 = fmaf(2.0f, kf, f);            // f + 2k*
    const float P  = fast_ex2(s1 * s2);            // exp2(-L f (f+2k*))
    const float ri = fast_ex2(-2.0f * s2);         // rho = exp2(2 L f)
    const float r2 = ri * ri;
    const float r4s = r2 * r2;
    unsigned long long u01, v01, r44, tap, tap2;
    asm("mov.b64 %0, {%1, %2};" : "=l"(u01) : "f"(P), "f"(P * ri));
    asm("mov.b64 %0, {%1, %2};" : "=l"(v01) : "f"(P * r2), "f"(P * r2 * ri));
    asm("mov.b64 %0, {%1, %1};" : "=l"(r44) : "f"(r4s));
#define RBF_STEP2(I, OFFU, OFFV)                                                \
    asm("ld.shared.b64 %0, [%1 + " OFFU "];" : "=l"(tap)  : "r"(addr));         \
    asm("ld.shared.b64 %0, [%1 + " OFFV "];" : "=l"(tap2) : "r"(addr));         \
    asm("fma.rn.f32x2 %0, %1, %2, %0;" : "+l"(feat2[I])   : "l"(u01), "l"(tap)); \
    asm("fma.rn.f32x2 %0, %1, %2, %0;" : "+l"(feat2[I+1]) : "l"(v01), "l"(tap2));\
    asm("mul.rn.f32x2 %0, %0, %1;" : "+l"(u01) : "l"(r44));                     \
    asm("mul.rn.f32x2 %0, %0, %1;" : "+l"(v01) : "l"(r44));
    RBF_STEP2(0, "0",   "-16")
    RBF_STEP2(2, "-32", "-48")
    RBF_STEP2(4, "-64", "-80")
    RBF_STEP2(6, "-96", "-112")
#undef RBF_STEP2
}

__global__ void __launch_bounds__(BLOCK, 12) fused_kernel(
    const float* __restrict__ pos,
    const int*   __restrict__ cs,
    const float* __restrict__ emb,
    const float* __restrict__ W1,   // [48][32] row-major
    const float* __restrict__ b1,   // [32]
    const float* __restrict__ W2,   // [32]
    const float* __restrict__ b2,   // [1]
    float*       __restrict__ out)
{
    __shared__ float  sbuf[WARPS_PER_BLOCK][JSL];       // 8 KB compaction (d^2)
    __shared__ float2 sU[64];                            // U[m]=(T[m],T[m-1]), m=u-14
    __shared__ float  sfeat[N_RBF][WARPS_PER_BLOCK + 1]; // [k][slice] padded

    const int tid  = threadIdx.x;
    const int wid  = tid >> 5;
    const int lane = tid & 31;
    const unsigned lmask = (1u << lane) - 1u;

    // Build U table: u -> m = u-14; entries underflow to exact 0 for |m|>12.
    if (tid < 64) {
        const float m0 = (float)(tid - 14);
        const float m1 = m0 - 1.0f;
        sU[tid] = make_float2(fast_ex2(-LOG2E * m0 * m0),
                              fast_ex2(-LOG2E * m1 * m1));
    }

    const int i = blockIdx.x;                     // this block's atom
    const float xi = __ldg(&pos[3 * i + 0]);
    const float yi = __ldg(&pos[3 * i + 1]);
    const float zi = __ldg(&pos[3 * i + 2]);

    unsigned long long feat2[8];
#pragma unroll
    for (int k = 0; k < 8; k++) feat2[k] = 0ull;

    float* buf = sbuf[wid];
    int cnt = 0;

    __syncthreads();                  // sU ready

    const uint32_t uBase = smem_u32(sU) + 14 * 8;

    // ---- dist pass: hoisted base pointer, immediate-offset loads ----
    const float* pw = pos + 3 * (wid * JSL + lane);   // this lane's j=+0 position
#pragma unroll 4
    for (int c = 0; c < NCHUNK; c++) {
        const float px = __ldg(pw + 96 * c + 0);      // 96 floats per 32-j chunk
        const float py = __ldg(pw + 96 * c + 1);
        const float pz = __ldg(pw + 96 * c + 2);
        const float dx = xi - px;
        const float dy = yi - py;
        const float dz = zi - pz;
        const float d2 = fmaf(dx, dx, fmaf(dy, dy, dz * dz));
        // 0 < d2 < 25  <=>  bits(d2)-1 <u bits(25)-1   (d2 non-negative finite)
        const bool pass = (__float_as_uint(d2) - 1u) < (D2_CUT_BITS - 1u);
        const unsigned m = __ballot_sync(0xFFFFFFFFu, pass);
        if (pass) buf[cnt + __popc(m & lmask)] = d2;
        cnt += __popc(m);
    }
    __syncwarp();

    // ---- dense exp phase: batches of 32 compacted pairs ----
    for (int b = 0; b < cnt; b += 32) {
        const float d2 = (b + lane < cnt) ? buf[b + lane] : PAD_D2;
        accum_rbf_f2(d2, uBase, feat2);
    }

    // ---- unpack to 16 scalars ----
    float feat[N_RBF];
#pragma unroll
    for (int k = 0; k < 8; k++) {
        asm("mov.b64 {%0, %1}, %2;"
            : "=f"(feat[2 * k]), "=f"(feat[2 * k + 1]) : "l"(feat2[k]));
    }

    // ---- reduce 16 sums across 32 lanes (collapse + index-fold) ----
#pragma unroll
    for (int k = 0; k < N_RBF; k++)
        feat[k] += __shfl_xor_sync(0xFFFFFFFFu, feat[k], 16);
#pragma unroll
    for (int bit = 8; bit >= 1; bit >>= 1) {
        const bool up = (lane & bit) != 0;
#pragma unroll
        for (int j = 0; j < bit; j++) {
            const float lo = feat[j], hi = feat[j + bit];
            const float send = up ? lo : hi;
            const float recv = __shfl_xor_sync(0xFFFFFFFFu, send, bit);
            feat[j] = (up ? hi : lo) + recv;
        }
    }
    if (lane < N_RBF) sfeat[lane][wid] = feat[0];
    __syncthreads();

    // ---- MLP on warp 0: lane = hidden unit ----
    if (wid == 0) {
        const int csi = (__ldg(cs) < 0) ? 0 : 1;
        float h = __ldg(&b1[lane]);
#pragma unroll
        for (int k = 0; k < N_RBF; k++) {
            const float fk = (sfeat[k][0] + sfeat[k][1])
                           + (sfeat[k][2] + sfeat[k][3]);
            h = fmaf(fk, __ldg(&W1[k * N_HIDDEN + lane]), h);
        }
#pragma unroll
        for (int m = 0; m < N_HIDDEN; m++)
            h = fmaf(__ldg(&emb[csi * N_HIDDEN + m]),
                     __ldg(&W1[(N_RBF + m) * N_HIDDEN + lane]), h);

        // silu(h) = h / (1 + e^{-h})
        const float s = h * fast_rcp(1.0f + fast_ex2(-LOG2E * h));
        float e = s * __ldg(&W2[lane]);
        e += __shfl_xor_sync(0xFFFFFFFFu, e, 16);
        e += __shfl_xor_sync(0xFFFFFFFFu, e, 8);
        e += __shfl_xor_sync(0xFFFFFFFFu, e, 4);
        e += __shfl_xor_sync(0xFFFFFFFFu, e, 2);
        e += __shfl_xor_sync(0xFFFFFFFFu, e, 1);

        // ---- fixed-point i64 accumulation (order-independent, deterministic) ----
        if (lane == 0) {
            const float partial = e + __ldg(b2);   // per-atom energy (+b2)
            const long long ll = (long long)((double)partial * FP_SCALE);
            atomicAdd(&g_isum[blockIdx.x & (NBANKS - 1)], (unsigned long long)ll);
            __threadfence();
            const unsigned v = atomicAdd(&g_count, 1u);
            if (v == (unsigned)(NBLOCKS - 1)) {    // last block finalizes
                __threadfence();
                long long tot = 0;
#pragma unroll
                for (int bk = 0; bk < NBANKS; bk++)
                    tot += (long long)atomicAdd(&g_isum[bk], 0ull);
                out[0] = (float)((double)tot * (1.0 / FP_SCALE));
#pragma unroll
                for (int bk = 0; bk < NBANKS; bk++) g_isum[bk] = 0ull;
                g_count = 0;                       // reset for next graph replay
            }
        }
    }
}

extern "C" void kernel_launch(void* const* d_in, const int* in_sizes, int n_in,
                              void* d_out, int out_size) {
    const float* pos = (const float*)d_in[0];
    const int*   cs  = (const int*)  d_in[1];
    const float* emb = (const float*)d_in[2];
    const float* W1  = (const float*)d_in[3];
    const float* b1  = (const float*)d_in[4];
    const float* W2  = (const float*)d_in[5];
    const float* b2  = (const float*)d_in[6];
    float* out = (float*)d_out;

    fused_kernel<<<NBLOCKS, BLOCK>>>(pos, cs, emb, W1, b1, W2, b2, out);
}

// round 17
// speedup vs baseline: 1.0607x; 1.0607x over previous
#include <cuda_runtime.h>
#include <cuda_bf16.h>
#include <cstdint>

// Problem constants (fixed by the reference)
#define N_ATOMS   2048
#define N_RBF     16
#define N_HIDDEN  32
// centers c_k = k/3 (linspace(0,5,16)), gamma = 9. With m = 3d = k* + f:
// g_k = e^{-(m-k)^2} = P * rho^k * T[k*-k],
//   P = exp2(-L f (f+2k*)), rho = exp2(2 L f), T[j] = e^{-j^2}
// Packed: feat2[i] = (feat[2i], feat[2i+1]); per step LDS.64 + FMA2 + MUL2.
#define LOG2E     (1.4426950408889634f)
#define MAGIC     (12582912.0f)        // 1.5*2^23 round-to-nearest trick
#define MAGIC_I   (0x4B400000)

#define WARPS_PER_BLOCK 4              // block = ONE atom, 4 j-slices
#define BLOCK           128
#define NBLOCKS         N_ATOMS                       // 2048 blocks
#define JSL             (N_ATOMS / WARPS_PER_BLOCK)   // 512 j's per slice
#define NCHUNK          (JSL / 32)                    // 16 chunks
#define PAD_D2          (177.78f)      // m=40 -> U reads land in zero entries
#define NBANKS          16
#define FP_SCALE        (4294967296.0) // 2^32 fixed-point scale

// device scratch (no runtime alloc allowed); zero-initialized at module load
__device__ unsigned long long g_isum[NBANKS];
__device__ unsigned int       g_count;

__device__ __forceinline__ float fast_ex2(float x) {
    float r; asm("ex2.approx.ftz.f32 %0, %1;" : "=f"(r) : "f"(x)); return r;
}
__device__ __forceinline__ float fast_rsq(float x) {
    float r; asm("rsqrt.approx.ftz.f32 %0, %1;" : "=f"(r) : "f"(x)); return r;
}
__device__ __forceinline__ float fast_rcp(float x) {
    float r; asm("rcp.approx.ftz.f32 %0, %1;" : "=f"(r) : "f"(x)); return r;
}
__device__ __forceinline__ uint32_t smem_u32(const void* p) {
    uint32_t a;
    asm("{ .reg .u64 t; cvta.to.shared.u64 t, %1; cvt.u32.u64 %0, t; }"
        : "=r"(a) : "l"(p));
    return a;
}

// Table-factored RBF, f32x2-packed, TWO independent ladder chains
// (u: feat2[0,2,4,6] stepping rho^4; v: feat2[1,3,5,7] stepping rho^4).
__device__ __forceinline__ void accum_rbf_f2(float d2, uint32_t uBase,
                                             unsigned long long feat2[8]) {
    const float d  = d2 * fast_rsq(d2);            // sqrt(d2)
    const float m3 = 3.0f * d;                     // m = 3d
    const float mm = m3 + MAGIC;                   // magic round-to-nearest
    const float kf = mm - MAGIC;                   // (float)k*
    const float f  = m3 - kf;                      // |f| <= 0.5
    const uint32_t addr = uBase + ((__float_as_uint(mm) - MAGIC_I) << 3);
    const float s2 = -LOG2E * f;
    const float s1 = fmaf(2.0f, kf, f);            // f + 2k*
    const float P  = fast_ex2(s1 * s2);            // exp2(-L f (f+2k*))
    const float ri = fast_ex2(-2.0f * s2);         // rho = exp2(2 L f)
    const float r2 = ri * ri;
    const float r4s = r2 * r2;
    unsigned long long u01, v01, r44, tap, tap2;
    asm("mov.b64 %0, {%1, %2};" : "=l"(u01) : "f"(P), "f"(P * ri));
    asm("mov.b64 %0, {%1, %2};" : "=l"(v01) : "f"(P * r2), "f"(P * r2 * ri));
    asm("mov.b64 %0, {%1, %1};" : "=l"(r44) : "f"(r4s));
#define RBF_STEP2(I, OFFU, OFFV)                                                \
    asm("ld.shared.b64 %0, [%1 + " OFFU "];" : "=l"(tap)  : "r"(addr));         \
    asm("ld.shared.b64 %0, [%1 + " OFFV "];" : "=l"(tap2) : "r"(addr));         \
    asm("fma.rn.f32x2 %0, %1, %2, %0;" : "+l"(feat2[I])   : "l"(u01), "l"(tap)); \
    asm("fma.rn.f32x2 %0, %1, %2, %0;" : "+l"(feat2[I+1]) : "l"(v01), "l"(tap2));\
    asm("mul.rn.f32x2 %0, %0, %1;" : "+l"(u01) : "l"(r44));                     \
    asm("mul.rn.f32x2 %0, %0, %1;" : "+l"(v01) : "l"(r44));
    RBF_STEP2(0, "0",   "-16")
    RBF_STEP2(2, "-32", "-48")
    RBF_STEP2(4, "-64", "-80")
    RBF_STEP2(6, "-96", "-112")
#undef RBF_STEP2
}

__global__ void __launch_bounds__(BLOCK, 12) fused_kernel(
    const float* __restrict__ pos,
    const int*   __restrict__ cs,
    const float* __restrict__ emb,
    const float* __restrict__ W1,   // [48][32] row-major
    const float* __restrict__ b1,   // [32]
    const float* __restrict__ W2,   // [32]
    const float* __restrict__ b2,   // [1]
    float*       __restrict__ out)
{
    __shared__ float  sbuf[WARPS_PER_BLOCK][JSL + 32];  // +32: PAD tail slots
    __shared__ float2 sU[64];                            // U[m]=(T[m],T[m-1]), m=u-14
    __shared__ float  sfeat[N_RBF][WARPS_PER_BLOCK + 1]; // [k][slice] padded

    const int tid  = threadIdx.x;
    const int wid  = tid >> 5;
    const int lane = tid & 31;
    const unsigned lmask = (1u << lane) - 1u;

    // Build U table: u -> m = u-14; entries underflow to exact 0 for |m|>12.
    if (tid < 64) {
        const float m0 = (float)(tid - 14);
        const float m1 = m0 - 1.0f;
        sU[tid] = make_float2(fast_ex2(-LOG2E * m0 * m0),
                              fast_ex2(-LOG2E * m1 * m1));
    }

    const int i = blockIdx.x;                     // this block's atom
    const float xi = __ldg(&pos[3 * i + 0]);
    const float yi = __ldg(&pos[3 * i + 1]);
    const float zi = __ldg(&pos[3 * i + 2]);

    unsigned long long feat2[8];
#pragma unroll
    for (int k = 0; k < 8; k++) feat2[k] = 0ull;

    float* buf = sbuf[wid];
    int cnt = 0;

    __syncthreads();                  // sU ready

    const uint32_t uBase = smem_u32(sU) + 14 * 8;

    // ---- dist pass: hoisted base pointer, immediate-offset loads ----
    const float* pw = pos + 3 * (wid * JSL + lane);   // this lane's j=+0 position
#pragma unroll 4
    for (int c = 0; c < NCHUNK; c++) {
        const float px = __ldg(pw + 96 * c + 0);      // 96 floats per 32-j chunk
        const float py = __ldg(pw + 96 * c + 1);
        const float pz = __ldg(pw + 96 * c + 2);
        const float dx = xi - px;
        const float dy = yi - py;
        const float dz = zi - pz;
        const float d2 = fmaf(dx, dx, fmaf(dy, dy, dz * dz));
        const bool pass = (d2 > 0.0f) && (d2 < 25.0f);
        const unsigned m = __ballot_sync(0xFFFFFFFFu, pass);
        if (pass) buf[cnt + __popc(m & lmask)] = d2;
        cnt += __popc(m);
    }
    buf[cnt + lane] = PAD_D2;         // pad tail -> dense loop needs no bounds test
    __syncwarp();

    // ---- dense exp phase: full batches of 32, pad pre-filled ----
    for (int b = 0; b < cnt; b += 32) {
        accum_rbf_f2(buf[b + lane], uBase, feat2);
    }

    // ---- unpack to 16 scalars ----
    float feat[N_RBF];
#pragma unroll
    for (int k = 0; k < 8; k++) {
        asm("mov.b64 {%0, %1}, %2;"
            : "=f"(feat[2 * k]), "=f"(feat[2 * k + 1]) : "l"(feat2[k]));
    }

    // ---- reduce 16 sums across 32 lanes (collapse + index-fold) ----
#pragma unroll
    for (int k = 0; k < N_RBF; k++)
        feat[k] += __shfl_xor_sync(0xFFFFFFFFu, feat[k], 16);
#pragma unroll
    for (int bit = 8; bit >= 1; bit >>= 1) {
        const bool up = (lane & bit) != 0;
#pragma unroll
        for (int j = 0; j < bit; j++) {
            const float lo = feat[j], hi = feat[j + bit];
            const float send = up ? lo : hi;
            const float recv = __shfl_xor_sync(0xFFFFFFFFu, send, bit);
            feat[j] = (up ? hi : lo) + recv;
        }
    }
    if (lane < N_RBF) sfeat[lane][wid] = feat[0];
    __syncthreads();

    // ---- MLP on warp 0: lane = hidden unit ----
    if (wid == 0) {
        const int csi = (__ldg(cs) < 0) ? 0 : 1;
        float h = __ldg(&b1[lane]);
#pragma unroll
        for (int k = 0; k < N_RBF; k++) {
            const float fk = (sfeat[k][0] + sfeat[k][1])
                           + (sfeat[k][2] + sfeat[k][3]);
            h = fmaf(fk, __ldg(&W1[k * N_HIDDEN + lane]), h);
        }
#pragma unroll
        for (int m = 0; m < N_HIDDEN; m++)
            h = fmaf(__ldg(&emb[csi * N_HIDDEN + m]),
                     __ldg(&W1[(N_RBF + m) * N_HIDDEN + lane]), h);

        // silu(h) = h / (1 + e^{-h})
        const float s = h * fast_rcp(1.0f + fast_ex2(-LOG2E * h));
        float e = s * __ldg(&W2[lane]);
        e += __shfl_xor_sync(0xFFFFFFFFu, e, 16);
        e += __shfl_xor_sync(0xFFFFFFFFu, e, 8);
        e += __shfl_xor_sync(0xFFFFFFFFu, e, 4);
        e += __shfl_xor_sync(0xFFFFFFFFu, e, 2);
        e += __shfl_xor_sync(0xFFFFFFFFu, e, 1);

        // ---- fixed-point i64 accumulation (order-independent, deterministic) ----
        if (lane == 0) {
            const float partial = e + __ldg(b2);   // per-atom energy (+b2)
            const long long ll = (long long)((double)partial * FP_SCALE);
            atomicAdd(&g_isum[blockIdx.x & (NBANKS - 1)], (unsigned long long)ll);
            __threadfence();
            const unsigned v = atomicAdd(&g_count, 1u);
            if (v == (unsigned)(NBLOCKS - 1)) {    // last block finalizes
                __threadfence();
                long long tot = 0;
#pragma unroll
                for (int bk = 0; bk < NBANKS; bk++)
                    tot += (long long)atomicAdd(&g_isum[bk], 0ull);
                out[0] = (float)((double)tot * (1.0 / FP_SCALE));
#pragma unroll
                for (int bk = 0; bk < NBANKS; bk++) g_isum[bk] = 0ull;
                g_count = 0;                       // reset for next graph replay
            }
        }
    }
}

extern "C" void kernel_launch(void* const* d_in, const int* in_sizes, int n_in,
                              void* d_out, int out_size) {
    const float* pos = (const float*)d_in[0];
    const int*   cs  = (const int*)  d_in[1];
    const float* emb = (const float*)d_in[2];
    const float* W1  = (const float*)d_in[3];
    const float* b1  = (const float*)d_in[4];
    const float* W2  = (const float*)d_in[5];
    const float* b2  = (const float*)d_in[6];
    float* out = (float*)d_out;

    fused_kernel<<<NBLOCKS, BLOCK>>>(pos, cs, emb, W1, b1, W2, b2, out);
}